// round 12
// baseline (speedup 1.0000x reference)
#include <cuda_runtime.h>
#include <cuda_bf16.h>

// PosMLP, two kernels:
//  A) gen_weights v6: block = 8 queries x 256 threads, 225 blocks.
//     Full w_gen (66.5 KB) staged in dynamic smem with row stride 260 floats
//     (lanes n -> banks 4 apart: LDS.128 at its 4-wavefront minimum).
//     Queries staged too; q reads are warp-uniform broadcasts (1 wf).
//     Thread (g, n) computes weights[2g]/[2g+1] at output n: 4 FFMA2 + 3 LDS.128
//     per 4 channels. No shuffles, no transpose kernel.
//  B) raster (round-6 proven body): thread = (q, w, h-half); 24 rows;
//     packed fma.rn.f32x2 inner loop.
//
// Shapes fixed by setup_inputs: B=2, Q=900 (NQ=1800), C=256, HIDDEN=16, H=W=48.

#define CC   256
#define NW   65
#define HD   16
#define HH   48
#define WW   48
#define NQ   1800
#define QB   8                    // queries per gen block
#define WSTRIDE 260               // smem w row stride (floats); 260%32=4 -> conflict-free LDS.128
#define GEN_SMEM_FLOATS (NW * WSTRIDE + QB * CC)
#define GEN_SMEM_BYTES  (GEN_SMEM_FLOATS * 4)   // 75,792 B

__device__ float g_wt[NQ * NW];   // 468 KB scratch (L2-resident)

// ---------------------------------------------------------------------------
// Packed fp32x2 FMA (sm_103a FFMA2 — only reachable via PTX fma.rn.f32x2).
// ---------------------------------------------------------------------------
union F2U { float2 f; unsigned long long u; };

__device__ __forceinline__ float2 ffma2(float2 a, float2 b, float2 c) {
    F2U A, B, C, D;
    A.f = a; B.f = b; C.f = c;
    asm("fma.rn.f32x2 %0, %1, %2, %3;"
        : "=l"(D.u) : "l"(A.u), "l"(B.u), "l"(C.u));
    return D.f;
}

// ---------------------------------------------------------------------------
// Kernel A: gen v6. 225 blocks x 256 threads, dynamic smem.
// ---------------------------------------------------------------------------
__global__ __launch_bounds__(256) void gen_weights_kernel(
    const float* __restrict__ queries,   // [1800][256]
    const float* __restrict__ w_gen,     // [65][256]
    const float* __restrict__ b_gen)     // [65]
{
    extern __shared__ float smem[];
    float* sw = smem;                    // [65][260]
    float* sq = smem + NW * WSTRIDE;     // [8][256]

    const int tid   = threadIdx.x;
    const int qbase = blockIdx.x * QB;

    // Stage w_gen: 65*64 = 4160 float4 elements.
    for (int gid = tid; gid < NW * 64; gid += 256) {
        const int n  = gid >> 6;
        const int c4 = gid & 63;
        *(float4*)&sw[n * WSTRIDE + c4 * 4] = ((const float4*)w_gen)[gid];
    }
    // Stage 8 query rows: 512 float4 elements.
    for (int gid = tid; gid < QB * 64; gid += 256) {
        const int r  = gid >> 6;
        const int c4 = gid & 63;
        *(float4*)&sq[r * CC + c4 * 4] =
            ((const float4*)(queries + (size_t)(qbase + r) * CC))[c4];
    }
    __syncthreads();

    const int g = tid >> 6;              // 0..3 -> queries 2g, 2g+1
    const int n = tid & 63;              // 0..63

    {
        const float* __restrict__ wrow = &sw[n * WSTRIDE];
        const float* __restrict__ qa   = &sq[(2 * g)     * CC];
        const float* __restrict__ qb   = &sq[(2 * g + 1) * CC];

        float2 a0 = make_float2(0.f, 0.f), a1 = make_float2(0.f, 0.f);
        float2 c0 = make_float2(0.f, 0.f), c1 = make_float2(0.f, 0.f);
        #pragma unroll 8
        for (int c4 = 0; c4 < 64; c4++) {
            const float4 wv = *(const float4*)&wrow[c4 * 4];
            const float4 x  = *(const float4*)&qa[c4 * 4];
            const float4 y  = *(const float4*)&qb[c4 * 4];
            a0 = ffma2(make_float2(x.x, x.y), make_float2(wv.x, wv.y), a0);
            a1 = ffma2(make_float2(x.z, x.w), make_float2(wv.z, wv.w), a1);
            c0 = ffma2(make_float2(y.x, y.y), make_float2(wv.x, wv.y), c0);
            c1 = ffma2(make_float2(y.z, y.w), make_float2(wv.z, wv.w), c1);
        }
        const float bg = b_gen[n];
        g_wt[(size_t)(qbase + 2 * g)     * NW + n] = (a0.x + a0.y) + (a1.x + a1.y) + bg;
        g_wt[(size_t)(qbase + 2 * g + 1) * NW + n] = (c0.x + c0.y) + (c1.x + c1.y) + bg;
    }

    // Output n = 64 (b2 row): first 8 threads take one extra output each.
    if (tid < QB) {
        const float* __restrict__ wrow = &sw[64 * WSTRIDE];
        const float* __restrict__ qq   = &sq[tid * CC];
        float2 a0 = make_float2(0.f, 0.f), a1 = make_float2(0.f, 0.f);
        #pragma unroll 8
        for (int c4 = 0; c4 < 64; c4++) {
            const float4 wv = *(const float4*)&wrow[c4 * 4];
            const float4 x  = *(const float4*)&qq[c4 * 4];
            a0 = ffma2(make_float2(x.x, x.y), make_float2(wv.x, wv.y), a0);
            a1 = ffma2(make_float2(x.z, x.w), make_float2(wv.z, wv.w), a1);
        }
        g_wt[(size_t)(qbase + tid) * NW + 64] =
            (a0.x + a0.y) + (a1.x + a1.y) + b_gen[64];
    }
}

// ---------------------------------------------------------------------------
// Kernel B: rasterizer (round-6 proven version, 62 regs).
// 1350 blocks x 128 threads. gtid -> q = gtid/96; hh = (gtid%96)/48; w = gtid%48.
// ---------------------------------------------------------------------------
__global__ __launch_bounds__(128) void raster_kernel(
    const float* __restrict__ pos,       // [1800][4] (cx, cy, bw, bh)
    float* __restrict__ out)             // [1800][48][48]
{
    const int gtid = blockIdx.x * 128 + threadIdx.x;
    const int q    = gtid / 96;
    const int rem  = gtid - q * 96;
    const int hh   = rem / 48;           // 0 or 1
    const int w    = rem - hh * 48;

    const float* __restrict__ wt = g_wt + q * NW;

    const float cx = pos[q * 4 + 0];
    const float cy = pos[q * 4 + 1];
    const float bw = pos[q * 4 + 2];
    const float bh = pos[q * 4 + 3];

    const float rx     = ((w + 0.5f) * (1.0f / WW) - cx) / bw;
    const float inv_bh = 1.0f / bh;

    // Pack per-pair (k = 2j, 2j+1) params. Fold rx*w1x + b1 into tw.
    float2 w1y2[HD / 2], tw2[HD / 2], w22[HD / 2];
    const float2 rx2 = make_float2(rx, rx);
    #pragma unroll
    for (int j = 0; j < HD / 2; j++) {
        w1y2[j]     = make_float2(wt[4 * j],     wt[4 * j + 2]);      // w1y_{2j}, w1y_{2j+1}
        float2 w1x2 = make_float2(wt[4 * j + 1], wt[4 * j + 3]);      // w1x_{2j}, w1x_{2j+1}
        float2 b12  = make_float2(wt[2 * HD + 2 * j], wt[2 * HD + 2 * j + 1]);
        tw2[j]      = ffma2(rx2, w1x2, b12);
        w22[j]      = make_float2(wt[3 * HD + 2 * j], wt[3 * HD + 2 * j + 1]);
    }
    const float b2 = wt[4 * HD];

    const int   h0    = hh * (HH / 2);
    const float y0    = ((h0 + 0.5f) * (1.0f / HH) - cy) * inv_bh;
    const float ystep = (1.0f / HH) * inv_bh;

    float* obase = out + (size_t)q * (HH * WW) + h0 * WW + w;

    #pragma unroll 2
    for (int h = 0; h < HH / 2; h++) {
        const float  ry  = fmaf((float)h, ystep, y0);
        const float2 ry2 = make_float2(ry, ry);
        float2 acc0 = make_float2(b2, 0.f);
        float2 acc1 = make_float2(0.f, 0.f);
        #pragma unroll
        for (int j = 0; j < HD / 2; j += 2) {
            float2 v0 = ffma2(ry2, w1y2[j],     tw2[j]);
            float2 v1 = ffma2(ry2, w1y2[j + 1], tw2[j + 1]);
            v0.x = fmaxf(v0.x, 0.f);  v0.y = fmaxf(v0.y, 0.f);
            v1.x = fmaxf(v1.x, 0.f);  v1.y = fmaxf(v1.y, 0.f);
            acc0 = ffma2(v0, w22[j],     acc0);
            acc1 = ffma2(v1, w22[j + 1], acc1);
        }
        obase[h * WW] = (acc0.x + acc0.y) + (acc1.x + acc1.y);
    }
}

extern "C" void kernel_launch(void* const* d_in, const int* in_sizes, int n_in,
                              void* d_out, int out_size) {
    const float* queries = (const float*)d_in[0];
    const float* pos     = (const float*)d_in[1];
    const float* w_gen   = (const float*)d_in[2];
    const float* b_gen   = (const float*)d_in[3];
    float* out = (float*)d_out;

    // Attribute set (idempotent, host-side, not an allocation).
    cudaFuncSetAttribute(gen_weights_kernel,
                         cudaFuncAttributeMaxDynamicSharedMemorySize,
                         GEN_SMEM_BYTES);

    gen_weights_kernel<<<NQ / QB, 256, GEN_SMEM_BYTES>>>(queries, w_gen, b_gen);
    raster_kernel<<<(NQ * WW * 2) / 128, 128>>>(pos, out);
}

// round 14
// speedup vs baseline: 2.1570x; 2.1570x over previous
#include <cuda_runtime.h>
#include <cuda_bf16.h>

// PosMLP fully fused, one launch. Block = 4 queries x 48 columns = 192 threads,
// 450 blocks.
//  Phase 1 (gen): weights[qi][65] = q[qi] @ w_gen^T + b_gen into smem.
//   - lane owns channels {32j + lane}: w LDG coalesced, q LDS conflict-free
//     (q hoisted to 8 regs per query once per warp).
//   - warp computes 4 n-rows per group, reduced with the 6-shfl 4-value
//     butterfly (results land on lanes 0/8/16/24). Groups ng = warp + 6k.
//  Phase 2 (raster): R6-proven FFMA2 body; thread = (qi, w), 48 rows.
//
// Shapes fixed by setup_inputs: B=2, Q=900 (NQ=1800), C=256, HIDDEN=16, H=W=48.

#define CC   256
#define NW   65
#define HD   16
#define HH   48
#define WW   48
#define QB   4
#define NTHREADS 192
#define NWARPS   6
#define NQ   1800
#define WTPAD 66          // sh_wt row stride: qi rows land in disjoint banks

// ---------------------------------------------------------------------------
// Packed fp32x2 FMA (sm_103a FFMA2 — only reachable via PTX fma.rn.f32x2).
// ---------------------------------------------------------------------------
union F2U { float2 f; unsigned long long u; };

__device__ __forceinline__ float2 ffma2(float2 a, float2 b, float2 c) {
    F2U A, B, C, D;
    A.f = a; B.f = b; C.f = c;
    asm("fma.rn.f32x2 %0, %1, %2, %3;"
        : "=l"(D.u) : "l"(A.u), "l"(B.u), "l"(C.u));
    return D.f;
}

__global__ __launch_bounds__(NTHREADS) void posmlp_kernel(
    const float* __restrict__ queries,  // [1800][256]
    const float* __restrict__ pos,      // [1800][4]  (cx, cy, bw, bh)
    const float* __restrict__ w_gen,    // [65][256]
    const float* __restrict__ b_gen,    // [65]
    float* __restrict__ out)            // [1800][48][48]
{
    __shared__ float sh_q[QB][CC];      // 4 KB
    __shared__ float sh_wt[QB][WTPAD];  // ~1 KB

    const int tid   = threadIdx.x;
    const int qbase = blockIdx.x * QB;

    // ---- Stage 4 query rows (1024 floats) ----
    {
        const float4* qsrc = (const float4*)(queries + (size_t)qbase * CC);
        float4* qdst = (float4*)&sh_q[0][0];
        #pragma unroll
        for (int i = tid; i < QB * CC / 4; i += NTHREADS)
            qdst[i] = qsrc[i];
    }
    __syncthreads();

    // ---- Phase 1: gen weights ----
    {
        const int warp = tid >> 5;
        const int lane = tid & 31;
        const bool lo16 = (lane & 16) == 0;
        const bool lo8  = (lane & 8) == 0;

        // Hoist query channels {32j + lane} for all 4 queries: 32 regs.
        float qv[QB][8];
        #pragma unroll
        for (int qi = 0; qi < QB; qi++)
            #pragma unroll
            for (int j = 0; j < 8; j++)
                qv[qi][j] = sh_q[qi][32 * j + lane];

        // Groups of 4 n-rows: ng = warp, warp+6, warp+12 (covers 0..16).
        for (int ng = warp; ng <= 16; ng += NWARPS) {
            const int nb = ng * 4;
            float s[QB][4];
            #pragma unroll
            for (int r = 0; r < 4; r++) {
                const int n = min(nb + r, NW - 1);   // clamp only at nb=64
                float wv[8];
                #pragma unroll
                for (int j = 0; j < 8; j++)
                    wv[j] = w_gen[n * CC + 32 * j + lane];
                #pragma unroll
                for (int qi = 0; qi < QB; qi++) {
                    float t0 = 0.f, t1 = 0.f;
                    t0 = fmaf(qv[qi][0], wv[0], t0);  t1 = fmaf(qv[qi][1], wv[1], t1);
                    t0 = fmaf(qv[qi][2], wv[2], t0);  t1 = fmaf(qv[qi][3], wv[3], t1);
                    t0 = fmaf(qv[qi][4], wv[4], t0);  t1 = fmaf(qv[qi][5], wv[5], t1);
                    t0 = fmaf(qv[qi][6], wv[6], t0);  t1 = fmaf(qv[qi][7], wv[7], t1);
                    s[qi][r] = t0 + t1;
                }
            }
            // 6-shfl reduction of 4 values per query; result r lands on lane 8r.
            #pragma unroll
            for (int qi = 0; qi < QB; qi++) {
                float a0 = lo16 ? s[qi][0] : s[qi][2];
                float b0 = lo16 ? s[qi][2] : s[qi][0];
                a0 += __shfl_xor_sync(0xffffffffu, b0, 16);
                float a1 = lo16 ? s[qi][1] : s[qi][3];
                float b1 = lo16 ? s[qi][3] : s[qi][1];
                a1 += __shfl_xor_sync(0xffffffffu, b1, 16);
                float c = lo8 ? a0 : a1;
                float d = lo8 ? a1 : a0;
                c += __shfl_xor_sync(0xffffffffu, d, 8);
                c += __shfl_xor_sync(0xffffffffu, c, 4);
                c += __shfl_xor_sync(0xffffffffu, c, 2);
                c += __shfl_xor_sync(0xffffffffu, c, 1);
                if ((lane & 7) == 0) {
                    const int n = nb + (lane >> 3);
                    if (n < NW)
                        sh_wt[qi][n] = c + b_gen[n];
                }
            }
        }
    }
    __syncthreads();

    // ---- Phase 2: raster (R6-proven FFMA2 body) ----
    const int qi  = tid / WW;           // 0..3
    const int w   = tid - qi * WW;      // 0..47
    const int qid = qbase + qi;

    const float* __restrict__ wt = sh_wt[qi];

    const float cx = pos[qid * 4 + 0];
    const float cy = pos[qid * 4 + 1];
    const float bw = pos[qid * 4 + 2];
    const float bh = pos[qid * 4 + 3];

    const float rx     = ((w + 0.5f) * (1.0f / WW) - cx) / bw;
    const float inv_bh = 1.0f / bh;

    // Pack per-pair (k = 2j, 2j+1) params. Fold rx*w1x + b1 into tw.
    float2 w1y2[HD / 2], tw2[HD / 2], w22[HD / 2];
    const float2 rx2 = make_float2(rx, rx);
    #pragma unroll
    for (int j = 0; j < HD / 2; j++) {
        w1y2[j]     = make_float2(wt[4 * j],     wt[4 * j + 2]);      // w1y_{2j}, w1y_{2j+1}
        float2 w1x2 = make_float2(wt[4 * j + 1], wt[4 * j + 3]);      // w1x_{2j}, w1x_{2j+1}
        float2 b12  = make_float2(wt[2 * HD + 2 * j], wt[2 * HD + 2 * j + 1]);
        tw2[j]      = ffma2(rx2, w1x2, b12);
        w22[j]      = make_float2(wt[3 * HD + 2 * j], wt[3 * HD + 2 * j + 1]);
    }
    const float b2 = wt[4 * HD];

    const float y0    = (0.5f * (1.0f / HH) - cy) * inv_bh;
    const float ystep = (1.0f / HH) * inv_bh;

    float* obase = out + (size_t)qid * (HH * WW) + w;

    #pragma unroll 2
    for (int h = 0; h < HH; h++) {
        const float  ry  = fmaf((float)h, ystep, y0);
        const float2 ry2 = make_float2(ry, ry);
        float2 acc0 = make_float2(b2, 0.f);
        float2 acc1 = make_float2(0.f, 0.f);
        #pragma unroll
        for (int j = 0; j < HD / 2; j += 2) {
            float2 v0 = ffma2(ry2, w1y2[j],     tw2[j]);
            float2 v1 = ffma2(ry2, w1y2[j + 1], tw2[j + 1]);
            v0.x = fmaxf(v0.x, 0.f);  v0.y = fmaxf(v0.y, 0.f);
            v1.x = fmaxf(v1.x, 0.f);  v1.y = fmaxf(v1.y, 0.f);
            acc0 = ffma2(v0, w22[j],     acc0);
            acc1 = ffma2(v1, w22[j + 1], acc1);
        }
        obase[h * WW] = (acc0.x + acc0.y) + (acc1.x + acc1.y);
    }
}

extern "C" void kernel_launch(void* const* d_in, const int* in_sizes, int n_in,
                              void* d_out, int out_size) {
    const float* queries = (const float*)d_in[0];
    const float* pos     = (const float*)d_in[1];
    const float* w_gen   = (const float*)d_in[2];
    const float* b_gen   = (const float*)d_in[3];
    float* out = (float*)d_out;

    posmlp_kernel<<<NQ / QB, NTHREADS>>>(queries, pos, w_gen, b_gen, out);
}

// round 16
// speedup vs baseline: 2.1898x; 1.0152x over previous
#include <cuda_runtime.h>
#include <cuda_bf16.h>

// PosMLP fully fused, one launch. Block = 2 queries x 48 columns x 2 row-halves
// = 192 threads, 900 blocks (172,800 threads; ~5-6 blocks/SM resident).
//  Phase 1 (gen): weights[qi][65] = q[qi] @ w_gen^T + b_gen into smem.
//   - lane owns channels {32j + lane}: w LDG coalesced, q hoisted to regs.
//   - warp computes 4 n-rows per group, 6-shfl 4-value butterfly reduction
//     (results land on lanes 0/8/16/24). Groups ng = warp + 6k (ng <= 16).
//  Phase 2 (raster): R6-proven FFMA2 body; thread = (qi, w, hh), 24 rows.
//
// Shapes fixed by setup_inputs: B=2, Q=900 (NQ=1800), C=256, HIDDEN=16, H=W=48.

#define CC   256
#define NW   65
#define HD   16
#define HH   48
#define WW   48
#define QB   2
#define NTHREADS 192
#define NWARPS   6
#define NQ   1800
#define WTPAD 66          // sh_wt row stride

// ---------------------------------------------------------------------------
// Packed fp32x2 FMA (sm_103a FFMA2 — only reachable via PTX fma.rn.f32x2).
// ---------------------------------------------------------------------------
union F2U { float2 f; unsigned long long u; };

__device__ __forceinline__ float2 ffma2(float2 a, float2 b, float2 c) {
    F2U A, B, C, D;
    A.f = a; B.f = b; C.f = c;
    asm("fma.rn.f32x2 %0, %1, %2, %3;"
        : "=l"(D.u) : "l"(A.u), "l"(B.u), "l"(C.u));
    return D.f;
}

__global__ __launch_bounds__(NTHREADS, 5) void posmlp_kernel(
    const float* __restrict__ queries,  // [1800][256]
    const float* __restrict__ pos,      // [1800][4]  (cx, cy, bw, bh)
    const float* __restrict__ w_gen,    // [65][256]
    const float* __restrict__ b_gen,    // [65]
    float* __restrict__ out)            // [1800][48][48]
{
    __shared__ float sh_q[QB][CC];      // 2 KB
    __shared__ float sh_wt[QB][WTPAD];  // ~0.5 KB

    const int tid   = threadIdx.x;
    const int qbase = blockIdx.x * QB;

    // ---- Stage 2 query rows (512 floats = 128 float4) ----
    if (tid < 128) {
        const float4* qsrc = (const float4*)(queries + (size_t)qbase * CC);
        ((float4*)&sh_q[0][0])[tid] = qsrc[tid];
    }
    __syncthreads();

    // ---- Phase 1: gen weights ----
    {
        const int warp = tid >> 5;
        const int lane = tid & 31;
        const bool lo16 = (lane & 16) == 0;
        const bool lo8  = (lane & 8) == 0;

        // Hoist query channels {32j + lane} for both queries: 16 regs.
        float qv[QB][8];
        #pragma unroll
        for (int qi = 0; qi < QB; qi++)
            #pragma unroll
            for (int j = 0; j < 8; j++)
                qv[qi][j] = sh_q[qi][32 * j + lane];

        // Groups of 4 n-rows: ng = warp, warp+6, warp+12 (covers 0..16).
        for (int ng = warp; ng <= 16; ng += NWARPS) {
            const int nb = ng * 4;
            float s[QB][4];
            #pragma unroll
            for (int r = 0; r < 4; r++) {
                const int n = min(nb + r, NW - 1);   // clamp only at nb=64
                float wv[8];
                #pragma unroll
                for (int j = 0; j < 8; j++)
                    wv[j] = w_gen[n * CC + 32 * j + lane];
                #pragma unroll
                for (int qi = 0; qi < QB; qi++) {
                    float t0 = 0.f, t1 = 0.f;
                    t0 = fmaf(qv[qi][0], wv[0], t0);  t1 = fmaf(qv[qi][1], wv[1], t1);
                    t0 = fmaf(qv[qi][2], wv[2], t0);  t1 = fmaf(qv[qi][3], wv[3], t1);
                    t0 = fmaf(qv[qi][4], wv[4], t0);  t1 = fmaf(qv[qi][5], wv[5], t1);
                    t0 = fmaf(qv[qi][6], wv[6], t0);  t1 = fmaf(qv[qi][7], wv[7], t1);
                    s[qi][r] = t0 + t1;
                }
            }
            // 6-shfl reduction of 4 values per query; result r lands on lane 8r.
            #pragma unroll
            for (int qi = 0; qi < QB; qi++) {
                float a0 = lo16 ? s[qi][0] : s[qi][2];
                float b0 = lo16 ? s[qi][2] : s[qi][0];
                a0 += __shfl_xor_sync(0xffffffffu, b0, 16);
                float a1 = lo16 ? s[qi][1] : s[qi][3];
                float b1 = lo16 ? s[qi][3] : s[qi][1];
                a1 += __shfl_xor_sync(0xffffffffu, b1, 16);
                float c = lo8 ? a0 : a1;
                float d = lo8 ? a1 : a0;
                c += __shfl_xor_sync(0xffffffffu, d, 8);
                c += __shfl_xor_sync(0xffffffffu, c, 4);
                c += __shfl_xor_sync(0xffffffffu, c, 2);
                c += __shfl_xor_sync(0xffffffffu, c, 1);
                if ((lane & 7) == 0) {
                    const int n = nb + (lane >> 3);
                    if (n < NW)
                        sh_wt[qi][n] = c + b_gen[n];
                }
            }
        }
    }
    __syncthreads();

    // ---- Phase 2: raster (R6-proven FFMA2 body), 24 rows per thread ----
    const int qi  = tid / 96;            // 0..1
    const int rem = tid - qi * 96;
    const int hh  = rem / 48;            // 0 or 1
    const int w   = rem - hh * 48;       // 0..47
    const int qid = qbase + qi;

    const float* __restrict__ wt = sh_wt[qi];

    const float cx = pos[qid * 4 + 0];
    const float cy = pos[qid * 4 + 1];
    const float bw = pos[qid * 4 + 2];
    const float bh = pos[qid * 4 + 3];

    const float rx     = ((w + 0.5f) * (1.0f / WW) - cx) / bw;
    const float inv_bh = 1.0f / bh;

    // Pack per-pair (k = 2j, 2j+1) params. Fold rx*w1x + b1 into tw.
    float2 w1y2[HD / 2], tw2[HD / 2], w22[HD / 2];
    const float2 rx2 = make_float2(rx, rx);
    #pragma unroll
    for (int j = 0; j < HD / 2; j++) {
        w1y2[j]     = make_float2(wt[4 * j],     wt[4 * j + 2]);      // w1y_{2j}, w1y_{2j+1}
        float2 w1x2 = make_float2(wt[4 * j + 1], wt[4 * j + 3]);      // w1x_{2j}, w1x_{2j+1}
        float2 b12  = make_float2(wt[2 * HD + 2 * j], wt[2 * HD + 2 * j + 1]);
        tw2[j]      = ffma2(rx2, w1x2, b12);
        w22[j]      = make_float2(wt[3 * HD + 2 * j], wt[3 * HD + 2 * j + 1]);
    }
    const float b2 = wt[4 * HD];

    const int   h0    = hh * (HH / 2);
    const float y0    = ((h0 + 0.5f) * (1.0f / HH) - cy) * inv_bh;
    const float ystep = (1.0f / HH) * inv_bh;

    float* obase = out + (size_t)qid * (HH * WW) + h0 * WW + w;

    #pragma unroll 2
    for (int h = 0; h < HH / 2; h++) {
        const float  ry  = fmaf((float)h, ystep, y0);
        const float2 ry2 = make_float2(ry, ry);
        float2 acc0 = make_float2(b2, 0.f);
        float2 acc1 = make_float2(0.f, 0.f);
        #pragma unroll
        for (int j = 0; j < HD / 2; j += 2) {
            float2 v0 = ffma2(ry2, w1y2[j],     tw2[j]);
            float2 v1 = ffma2(ry2, w1y2[j + 1], tw2[j + 1]);
            v0.x = fmaxf(v0.x, 0.f);  v0.y = fmaxf(v0.y, 0.f);
            v1.x = fmaxf(v1.x, 0.f);  v1.y = fmaxf(v1.y, 0.f);
            acc0 = ffma2(v0, w22[j],     acc0);
            acc1 = ffma2(v1, w22[j + 1], acc1);
        }
        obase[h * WW] = (acc0.x + acc0.y) + (acc1.x + acc1.y);
    }
}

extern "C" void kernel_launch(void* const* d_in, const int* in_sizes, int n_in,
                              void* d_out, int out_size) {
    const float* queries = (const float*)d_in[0];
    const float* pos     = (const float*)d_in[1];
    const float* w_gen   = (const float*)d_in[2];
    const float* b_gen   = (const float*)d_in[3];
    float* out = (float*)d_out;

    posmlp_kernel<<<NQ / QB, NTHREADS>>>(queries, pos, w_gen, b_gen, out);
}